// round 11
// baseline (speedup 1.0000x reference)
#include <cuda_runtime.h>

// Fixed shapes: B=128, L=512, D=256, T=64, G=8
#define B_ 128
#define L_ 512
#define D_ 256
#define T_ 64
#define G_ 8
#define D4_ (D_/4)              // 64
#define NPOOL (B_*T_*D_)        // 2,097,152
#define NFULL (B_*L_*D_)        // 16,777,216
#define NFULL4 (NFULL/4)        // 4,194,304 float4 per modality
#define PARTS_ 16               // blocks per batch (each covers 4 t-rows)

// Scratch (__device__ globals; allocation-free rule)
__device__ float g_c3[NPOOL];                 // 8 MB : sigmoid(conv)/3
__device__ float g_rowsum[B_ * T_];           // 32 KB
__device__ float g_colpart[B_ * PARTS_ * D_]; // 2 MB
__device__ float g_h3[B_ * T_];               // 32 KB
__device__ float g_w3[B_ * D_];               // 128 KB

__device__ __forceinline__ float sigmoidf_(float x) {
    return 1.0f / (1.0f + __expf(-x));
}

__device__ __forceinline__ float4 ldcs4(const float4* p) {
    float4 r;
    asm volatile("ld.global.cs.v4.f32 {%0,%1,%2,%3}, [%4];"
                 : "=f"(r.x), "=f"(r.y), "=f"(r.z), "=f"(r.w) : "l"(p));
    return r;
}

// ---------------------------------------------------------------------------
// Kernel 1: pooling + c3 + in-block hw reductions. (measured: 25.4us, 68% DRAM)
// ---------------------------------------------------------------------------
__global__ void __launch_bounds__(256) pool_kernel(const float* __restrict__ aco,
                                                   const float* __restrict__ vis,
                                                   const float* __restrict__ conv_w,
                                                   const float* __restrict__ conv_b) {
    int tid = threadIdx.x;
    int idx = blockIdx.x * 256 + tid;      // over B*T*D/4
    int d4 = idx & (D4_ - 1);
    int t  = (idx >> 6) & (T_ - 1);
    int b  = idx >> 12;
    int lane = tid & 31;
    int wrp  = tid >> 5;

    __shared__ float4 s_col[256];
    __shared__ float  s_warp[8];

    size_t base = (size_t)b * L_ * D4_ + (size_t)t * G_ * D4_ + d4;
    const float4* a4 = reinterpret_cast<const float4*>(aco) + base;
    const float4* v4 = reinterpret_cast<const float4*>(vis) + base;

    float4 sa = make_float4(0.f, 0.f, 0.f, 0.f);
    float4 sv = make_float4(0.f, 0.f, 0.f, 0.f);
#pragma unroll
    for (int g = 0; g < G_; g++) {
        float4 x = ldcs4(a4 + g * D4_);
        float4 y = ldcs4(v4 + g * D4_);
        sa.x += x.x; sa.y += x.y; sa.z += x.z; sa.w += x.w;
        sv.x += y.x; sv.y += y.y; sv.z += y.z; sv.w += y.w;
    }
    const float inv = 1.0f / (float)G_;
    sa.x *= inv; sa.y *= inv; sa.z *= inv; sa.w *= inv;
    sv.x *= inv; sv.y *= inv; sv.z *= inv; sv.w *= inv;

    float4 hw;
    hw.x = 0.5f * (sa.x + sv.x);
    hw.y = 0.5f * (sa.y + sv.y);
    hw.z = 0.5f * (sa.z + sv.z);
    hw.w = 0.5f * (sa.w + sv.w);

    const float cw0 = __ldg(conv_w + 0);
    const float cw1 = __ldg(conv_w + 1);
    const float cb  = __ldg(conv_b + 0);
    const float third = 1.0f / 3.0f;
    float4 c3;
    c3.x = sigmoidf_(fmaf(cw0, sa.x, fmaf(cw1, sv.x, cb))) * third;
    c3.y = sigmoidf_(fmaf(cw0, sa.y, fmaf(cw1, sv.y, cb))) * third;
    c3.z = sigmoidf_(fmaf(cw0, sa.z, fmaf(cw1, sv.z, cb))) * third;
    c3.w = sigmoidf_(fmaf(cw0, sa.w, fmaf(cw1, sv.w, cb))) * third;
    reinterpret_cast<float4*>(g_c3)[idx] = c3;

    float rs = (hw.x + hw.y) + (hw.z + hw.w);
#pragma unroll
    for (int o = 16; o > 0; o >>= 1) rs += __shfl_down_sync(0xffffffffu, rs, o);
    if (lane == 0) s_warp[wrp] = rs;

    s_col[tid] = hw;
    __syncthreads();

    if (tid < 4) {
        g_rowsum[b * T_ + ((blockIdx.x & (PARTS_ - 1)) * 4 + tid)] =
            s_warp[2 * tid] + s_warp[2 * tid + 1];
    }
    if (tid < 64) {
        float4 c0 = s_col[tid];
        float4 c1 = s_col[64 + tid];
        float4 c2 = s_col[128 + tid];
        float4 c3v = s_col[192 + tid];
        float4 cp;
        cp.x = (c0.x + c1.x) + (c2.x + c3v.x);
        cp.y = (c0.y + c1.y) + (c2.y + c3v.y);
        cp.z = (c0.z + c1.z) + (c2.z + c3v.z);
        cp.w = (c0.w + c1.w) + (c2.w + c3v.w);
        reinterpret_cast<float4*>(g_colpart)[blockIdx.x * 64 + tid] = cp;
    }
}

// ---------------------------------------------------------------------------
// Kernel 2: finish means + two small matvecs. One block per batch.
// ---------------------------------------------------------------------------
__global__ void __launch_bounds__(256) reduce_kernel(const float* __restrict__ Wh,
                                                     const float* __restrict__ bh,
                                                     const float* __restrict__ Ww,
                                                     const float* __restrict__ bw) {
    int b   = blockIdx.x;
    int tid = threadIdx.x;

    __shared__ float s_hwm_t[T_];
    __shared__ float s_hwm_d[D_];

    if (tid < T_)
        s_hwm_t[tid] = g_rowsum[b * T_ + tid] * (1.0f / (float)D_);

    {
        const float* cp = g_colpart + b * PARTS_ * D_ + tid;
        float cs = 0.f;
#pragma unroll
        for (int p = 0; p < PARTS_; p++) cs += cp[p * D_];
        s_hwm_d[tid] = cs * (1.0f / (float)T_);
    }
    __syncthreads();

    const float third = 1.0f / 3.0f;

    if (tid < T_) {
        float acc = __ldg(bh + tid);
        const float* wr = Wh + tid * T_;
#pragma unroll 8
        for (int j = 0; j < T_; j++) acc = fmaf(s_hwm_t[j], __ldg(wr + j), acc);
        g_h3[b * T_ + tid] = sigmoidf_(acc) * third;
    }
    {
        float acc = __ldg(bw + tid);
        const float* wr = Ww + tid * D_;
#pragma unroll 8
        for (int j = 0; j < D_; j++) acc = fmaf(s_hwm_d[j], __ldg(wr + j), acc);
        g_w3[b * D_ + tid] = sigmoidf_(acc) * third;
    }
}

// ---------------------------------------------------------------------------
// Kernel 3: apply, tiled by (b, 4t). Thread owns one (t,d4) scale vector,
// computed ONCE, reused across all G=8 sequence positions. Plain stores.
// ---------------------------------------------------------------------------
__global__ void __launch_bounds__(256) apply_kernel(const float* __restrict__ aco,
                                                    const float* __restrict__ vis,
                                                    const int* __restrict__ isbag,
                                                    float* __restrict__ out) {
    int tid  = threadIdx.x;
    int part = blockIdx.x & (PARTS_ - 1);
    int b    = blockIdx.x >> 4;            // PARTS_ = 16
    int t    = part * 4 + (tid >> 6);      // local t row = tid>>6
    int d4   = tid & (D4_ - 1);

    // --- scale vector, computed once per thread -----------------------------
    float4 c = __ldg(reinterpret_cast<const float4*>(g_c3) + ((b * T_ + t) << 6) + d4);
    float4 w = __ldg(reinterpret_cast<const float4*>(g_w3) + b * D4_ + d4);
    float  h = __ldg(g_h3 + b * T_ + t);
    float4 s = make_float4(h + w.x + c.x, h + w.y + c.y, h + w.z + c.z, h + w.w + c.w);

    // --- masks for the 8 sequence positions of this t (broadcast loads) -----
    const int4* mb = reinterpret_cast<const int4*>(isbag + b * L_ + t * G_);
    int4 m03 = __ldg(mb);
    int4 m47 = __ldg(mb + 1);
    int mk[8] = {m03.x, m03.y, m03.z, m03.w, m47.x, m47.y, m47.z, m47.w};

    const float4* a4 = reinterpret_cast<const float4*>(aco);
    const float4* v4 = reinterpret_cast<const float4*>(vis);
    float4* o4 = reinterpret_cast<float4*>(out);

    int base = b * (L_ * D4_) + t * (G_ * D4_) + d4;   // g stride = D4_

#pragma unroll
    for (int half = 0; half < 2; half++) {
        int g0 = half * 4;
        float4 a[4], v[4];
#pragma unroll
        for (int g = 0; g < 4; g++) a[g] = ldcs4(a4 + base + (g0 + g) * D4_);
#pragma unroll
        for (int g = 0; g < 4; g++) v[g] = ldcs4(v4 + base + (g0 + g) * D4_);

#pragma unroll
        for (int g = 0; g < 4; g++) {
            int idx = base + (g0 + g) * D4_;
            bool m = (mk[g0 + g] == 1);
            float sx = m ? s.x : 1.0f;
            float sy = m ? s.y : 1.0f;
            float sz = m ? s.z : 1.0f;
            float sw = m ? s.w : 1.0f;
            o4[idx]          = make_float4(a[g].x * sx, a[g].y * sy, a[g].z * sz, a[g].w * sw);
            o4[idx + NFULL4] = make_float4(v[g].x * sx, v[g].y * sy, v[g].z * sz, v[g].w * sw);
        }
    }
}

// ---------------------------------------------------------------------------
extern "C" void kernel_launch(void* const* d_in, const int* in_sizes, int n_in,
                              void* d_out, int out_size) {
    const float* aco    = (const float*)d_in[0];
    const float* vis    = (const float*)d_in[1];
    const int*   isbag  = (const int*)  d_in[2];
    const float* Wh     = (const float*)d_in[3];
    const float* bh     = (const float*)d_in[4];
    const float* Ww     = (const float*)d_in[5];
    const float* bw     = (const float*)d_in[6];
    const float* conv_w = (const float*)d_in[7];
    const float* conv_b = (const float*)d_in[8];
    float* out = (float*)d_out;

    (void)in_sizes; (void)n_in; (void)out_size;

    pool_kernel<<<NPOOL / 4 / 256, 256>>>(aco, vis, conv_w, conv_b);
    reduce_kernel<<<B_, 256>>>(Wh, bh, Ww, bw);
    apply_kernel<<<B_ * PARTS_, 256>>>(aco, vis, isbag, out);
}

// round 12
// speedup vs baseline: 1.3591x; 1.3591x over previous
#include <cuda_runtime.h>

// Fixed shapes: B=128, L=512, D=256, T=64, G=8
#define B_ 128
#define L_ 512
#define D_ 256
#define T_ 64
#define G_ 8
#define D4_ (D_/4)              // 64
#define NPOOL (B_*T_*D_)        // 2,097,152
#define NFULL (B_*L_*D_)        // 16,777,216
#define NFULL4 (NFULL/4)        // 4,194,304 float4 per modality
#define PARTS_ 16               // pool blocks per batch (each covers 4 t-rows)

// Scratch (__device__ globals; allocation-free rule)
__device__ float g_c3[NPOOL];                 // 8 MB : sigmoid(conv)/3
__device__ float g_rowsum[B_ * T_];           // 32 KB
__device__ float g_colpart[B_ * PARTS_ * D_]; // 2 MB
__device__ float g_h3[B_ * T_];               // 32 KB
__device__ float g_w3[B_ * D_];               // 128 KB
__device__ float g_WwT[D_ * D_];              // 256 KB : Ww transposed
__device__ float g_WhT[T_ * T_];              // 16 KB  : Wh transposed

__device__ __forceinline__ float sigmoidf_(float x) {
    return 1.0f / (1.0f + __expf(-x));
}

__device__ __forceinline__ float4 ldcs4(const float4* p) {
    float4 r;
    asm volatile("ld.global.cs.v4.f32 {%0,%1,%2,%3}, [%4];"
                 : "=f"(r.x), "=f"(r.y), "=f"(r.z), "=f"(r.w) : "l"(p));
    return r;
}
__device__ __forceinline__ void stcs4(float4* p, float4 v) {
    asm volatile("st.global.cs.v4.f32 [%0], {%1,%2,%3,%4};"
                 :: "l"(p), "f"(v.x), "f"(v.y), "f"(v.z), "f"(v.w));
}

// ---------------------------------------------------------------------------
// Kernel 0: one-shot transpose of Ww (256x256) and Wh (64x64).
// 32x32 tiles; blocks 0..63 = Ww, 64..67 = Wh. 256 threads = 32x8, 4 rows/thr.
// ---------------------------------------------------------------------------
__global__ void __launch_bounds__(256) transpose_kernel(const float* __restrict__ Wh,
                                                        const float* __restrict__ Ww) {
    __shared__ float tile[32][33];
    int x  = threadIdx.x & 31;
    int y8 = threadIdx.x >> 5;            // 0..7

    const float* src; float* dst; int n, tx, ty;
    if (blockIdx.x < 64) {                // Ww: 8x8 tiles of 32
        src = Ww; dst = g_WwT; n = D_;
        tx = blockIdx.x & 7; ty = blockIdx.x >> 3;
    } else {                              // Wh: 2x2 tiles of 32
        int k = blockIdx.x - 64;
        src = Wh; dst = g_WhT; n = T_;
        tx = k & 1; ty = k >> 1;
    }

#pragma unroll
    for (int r = 0; r < 4; r++) {
        int row = y8 + r * 8;             // 0..31
        tile[row][x] = src[(ty * 32 + row) * n + tx * 32 + x];
    }
    __syncthreads();
#pragma unroll
    for (int r = 0; r < 4; r++) {
        int row = y8 + r * 8;
        dst[(tx * 32 + row) * n + ty * 32 + x] = tile[x][row];
    }
}

// ---------------------------------------------------------------------------
// Kernel 1: pooling + c3 + in-block hw reductions. (measured 25.2us, 69% DRAM)
// ---------------------------------------------------------------------------
__global__ void __launch_bounds__(256) pool_kernel(const float* __restrict__ aco,
                                                   const float* __restrict__ vis,
                                                   const float* __restrict__ conv_w,
                                                   const float* __restrict__ conv_b) {
    int tid = threadIdx.x;
    int idx = blockIdx.x * 256 + tid;      // over B*T*D/4
    int d4 = idx & (D4_ - 1);
    int t  = (idx >> 6) & (T_ - 1);
    int b  = idx >> 12;
    int lane = tid & 31;
    int wrp  = tid >> 5;

    __shared__ float4 s_col[256];
    __shared__ float  s_warp[8];

    size_t base = (size_t)b * L_ * D4_ + (size_t)t * G_ * D4_ + d4;
    const float4* a4 = reinterpret_cast<const float4*>(aco) + base;
    const float4* v4 = reinterpret_cast<const float4*>(vis) + base;

    float4 sa = make_float4(0.f, 0.f, 0.f, 0.f);
    float4 sv = make_float4(0.f, 0.f, 0.f, 0.f);
#pragma unroll
    for (int g = 0; g < G_; g++) {
        float4 x = ldcs4(a4 + g * D4_);
        float4 y = ldcs4(v4 + g * D4_);
        sa.x += x.x; sa.y += x.y; sa.z += x.z; sa.w += x.w;
        sv.x += y.x; sv.y += y.y; sv.z += y.z; sv.w += y.w;
    }
    const float inv = 1.0f / (float)G_;
    sa.x *= inv; sa.y *= inv; sa.z *= inv; sa.w *= inv;
    sv.x *= inv; sv.y *= inv; sv.z *= inv; sv.w *= inv;

    float4 hw;
    hw.x = 0.5f * (sa.x + sv.x);
    hw.y = 0.5f * (sa.y + sv.y);
    hw.z = 0.5f * (sa.z + sv.z);
    hw.w = 0.5f * (sa.w + sv.w);

    const float cw0 = __ldg(conv_w + 0);
    const float cw1 = __ldg(conv_w + 1);
    const float cb  = __ldg(conv_b + 0);
    const float third = 1.0f / 3.0f;
    float4 c3;
    c3.x = sigmoidf_(fmaf(cw0, sa.x, fmaf(cw1, sv.x, cb))) * third;
    c3.y = sigmoidf_(fmaf(cw0, sa.y, fmaf(cw1, sv.y, cb))) * third;
    c3.z = sigmoidf_(fmaf(cw0, sa.z, fmaf(cw1, sv.z, cb))) * third;
    c3.w = sigmoidf_(fmaf(cw0, sa.w, fmaf(cw1, sv.w, cb))) * third;
    reinterpret_cast<float4*>(g_c3)[idx] = c3;

    float rs = (hw.x + hw.y) + (hw.z + hw.w);
#pragma unroll
    for (int o = 16; o > 0; o >>= 1) rs += __shfl_down_sync(0xffffffffu, rs, o);
    if (lane == 0) s_warp[wrp] = rs;

    s_col[tid] = hw;
    __syncthreads();

    if (tid < 4) {
        g_rowsum[b * T_ + ((blockIdx.x & (PARTS_ - 1)) * 4 + tid)] =
            s_warp[2 * tid] + s_warp[2 * tid + 1];
    }
    if (tid < 64) {
        float4 c0 = s_col[tid];
        float4 c1 = s_col[64 + tid];
        float4 c2 = s_col[128 + tid];
        float4 c3v = s_col[192 + tid];
        float4 cp;
        cp.x = (c0.x + c1.x) + (c2.x + c3v.x);
        cp.y = (c0.y + c1.y) + (c2.y + c3v.y);
        cp.z = (c0.z + c1.z) + (c2.z + c3v.z);
        cp.w = (c0.w + c1.w) + (c2.w + c3v.w);
        reinterpret_cast<float4*>(g_colpart)[blockIdx.x * 64 + tid] = cp;
    }
}

// ---------------------------------------------------------------------------
// Kernel 2: finish means + coalesced matvecs via transposed weights.
// Outer-product form: acc[i] += hwm[j] * WT[j*n + i]  -> fully coalesced LDG,
// smem-broadcast multiplier, no sector amplification (was 8x -> ~30us).
// ---------------------------------------------------------------------------
__global__ void __launch_bounds__(256) reduce_kernel(const float* __restrict__ bh,
                                                     const float* __restrict__ bw) {
    int b   = blockIdx.x;
    int tid = threadIdx.x;               // 0..255 (== output index i)

    __shared__ float s_hwm_t[T_];
    __shared__ float s_hwm_d[D_];

    if (tid < T_)
        s_hwm_t[tid] = g_rowsum[b * T_ + tid] * (1.0f / (float)D_);

    {
        const float* cp = g_colpart + b * PARTS_ * D_ + tid;
        float cs = 0.f;
#pragma unroll
        for (int p = 0; p < PARTS_; p++) cs += cp[p * D_];
        s_hwm_d[tid] = cs * (1.0f / (float)T_);
    }
    __syncthreads();

    const float third = 1.0f / 3.0f;

    // w3[i] = sigmoid(sum_j hwm_d[j] * WwT[j, i] + bw[i]) / 3  (two accs for ILP)
    {
        float acc0 = __ldg(bw + tid);
        float acc1 = 0.f;
        const float* wt = g_WwT + tid;
#pragma unroll 8
        for (int j = 0; j < D_; j += 2) {
            acc0 = fmaf(s_hwm_d[j],     __ldg(wt + j * D_),        acc0);
            acc1 = fmaf(s_hwm_d[j + 1], __ldg(wt + (j + 1) * D_),  acc1);
        }
        g_w3[b * D_ + tid] = sigmoidf_(acc0 + acc1) * third;
    }
    // h3[i] = sigmoid(sum_j hwm_t[j] * WhT[j, i] + bh[i]) / 3   (threads 0..63)
    if (tid < T_) {
        float acc0 = __ldg(bh + tid);
        float acc1 = 0.f;
        const float* wt = g_WhT + tid;
#pragma unroll 8
        for (int j = 0; j < T_; j += 2) {
            acc0 = fmaf(s_hwm_t[j],     __ldg(wt + j * T_),        acc0);
            acc1 = fmaf(s_hwm_t[j + 1], __ldg(wt + (j + 1) * T_),  acc1);
        }
        g_h3[b * T_ + tid] = sigmoidf_(acc0 + acc1) * third;
    }
}

// ---------------------------------------------------------------------------
// Kernel 3: apply (R7 variant — best measured). ILP=4 linear tiles, .cs
// loads/stores on the 256 MB bulk; scale composed inline from L2-hot tensors.
// ---------------------------------------------------------------------------
__global__ void __launch_bounds__(256) apply_kernel(const float* __restrict__ aco,
                                                    const float* __restrict__ vis,
                                                    const int* __restrict__ isbag,
                                                    float* __restrict__ out) {
    int base = blockIdx.x * 1024 + threadIdx.x;   // block tile = 1024 float4

    const float4* a4 = reinterpret_cast<const float4*>(aco);
    const float4* v4 = reinterpret_cast<const float4*>(vis);
    const float4* c4 = reinterpret_cast<const float4*>(g_c3);
    const float4* w4 = reinterpret_cast<const float4*>(g_w3);
    float4* o4 = reinterpret_cast<float4*>(out);

    float4 a[4], v[4];
#pragma unroll
    for (int k = 0; k < 4; k++) a[k] = ldcs4(a4 + base + k * 256);
#pragma unroll
    for (int k = 0; k < 4; k++) v[k] = ldcs4(v4 + base + k * 256);

#pragma unroll
    for (int k = 0; k < 4; k++) {
        int idx = base + k * 256;
        int d4 = idx & (D4_ - 1);
        int l  = (idx >> 6) & (L_ - 1);
        int b  = idx >> 15;            // L_*D4_ = 32768 float4 per batch
        int t  = l >> 3;               // t = l / G

        float4 c = __ldg(c4 + ((b * T_ + t) << 6) + d4);
        float4 w = __ldg(w4 + b * D4_ + d4);
        float  h = __ldg(g_h3 + b * T_ + t);
        bool   m = (__ldg(isbag + b * L_ + l) == 1);

        float sx = m ? (h + w.x + c.x) : 1.0f;
        float sy = m ? (h + w.y + c.y) : 1.0f;
        float sz = m ? (h + w.z + c.z) : 1.0f;
        float sw = m ? (h + w.w + c.w) : 1.0f;

        stcs4(o4 + idx,          make_float4(a[k].x * sx, a[k].y * sy, a[k].z * sz, a[k].w * sw));
        stcs4(o4 + idx + NFULL4, make_float4(v[k].x * sx, v[k].y * sy, v[k].z * sz, v[k].w * sw));
    }
}

// ---------------------------------------------------------------------------
extern "C" void kernel_launch(void* const* d_in, const int* in_sizes, int n_in,
                              void* d_out, int out_size) {
    const float* aco    = (const float*)d_in[0];
    const float* vis    = (const float*)d_in[1];
    const int*   isbag  = (const int*)  d_in[2];
    const float* Wh     = (const float*)d_in[3];
    const float* bh     = (const float*)d_in[4];
    const float* Ww     = (const float*)d_in[5];
    const float* bw     = (const float*)d_in[6];
    const float* conv_w = (const float*)d_in[7];
    const float* conv_b = (const float*)d_in[8];
    float* out = (float*)d_out;

    (void)in_sizes; (void)n_in; (void)out_size;

    transpose_kernel<<<68, 256>>>(Wh, Ww);
    pool_kernel<<<NPOOL / 4 / 256, 256>>>(aco, vis, conv_w, conv_b);
    reduce_kernel<<<B_, 256>>>(bh, bw);
    apply_kernel<<<NFULL4 / 1024, 256>>>(aco, vis, isbag, out);
}

// round 13
// speedup vs baseline: 1.3728x; 1.0101x over previous
#include <cuda_runtime.h>

// Fixed shapes: B=128, L=512, D=256, T=64, G=8
#define B_ 128
#define L_ 512
#define D_ 256
#define T_ 64
#define G_ 8
#define D4_ (D_/4)              // 64
#define NPOOL (B_*T_*D_)        // 2,097,152
#define NFULL (B_*L_*D_)        // 16,777,216
#define NFULL4 (NFULL/4)        // 4,194,304 float4 per modality
#define PARTS_ 16               // pool blocks per batch (each covers 4 t-rows)
#define POOL_BLOCKS (NPOOL/4/256)   // 2048
#define TRANS_BLOCKS 68

// Scratch (__device__ globals; allocation-free rule)
__device__ float g_c3[NPOOL];                 // 8 MB : sigmoid(conv)/3
__device__ float g_rowsum[B_ * T_];           // 32 KB
__device__ float g_colpart[B_ * PARTS_ * D_]; // 2 MB
__device__ float g_h3[B_ * T_];               // 32 KB
__device__ float g_w3[B_ * D_];               // 128 KB
__device__ float g_WwT[D_ * D_];              // 256 KB : Ww transposed
__device__ float g_WhT[T_ * T_];              // 16 KB  : Wh transposed

__device__ __forceinline__ float sigmoidf_(float x) {
    return 1.0f / (1.0f + __expf(-x));
}

__device__ __forceinline__ float4 ldcs4(const float4* p) {
    float4 r;
    asm volatile("ld.global.cs.v4.f32 {%0,%1,%2,%3}, [%4];"
                 : "=f"(r.x), "=f"(r.y), "=f"(r.z), "=f"(r.w) : "l"(p));
    return r;
}
__device__ __forceinline__ void stcs4(float4* p, float4 v) {
    asm volatile("st.global.cs.v4.f32 [%0], {%1,%2,%3,%4};"
                 :: "l"(p), "f"(v.x), "f"(v.y), "f"(v.z), "f"(v.w));
}

// ---------------------------------------------------------------------------
// Kernel 1: pooling + c3 + in-block hw reductions, with the weight transpose
// folded in as trailing blocks (runs concurrently with the streaming waves).
// ---------------------------------------------------------------------------
__global__ void __launch_bounds__(256) pool_kernel(const float* __restrict__ aco,
                                                   const float* __restrict__ vis,
                                                   const float* __restrict__ conv_w,
                                                   const float* __restrict__ conv_b,
                                                   const float* __restrict__ Wh,
                                                   const float* __restrict__ Ww) {
    int tid = threadIdx.x;

    // ---- trailing blocks: 32x32 tiled transpose of Ww (64 tiles) + Wh (4) --
    if (blockIdx.x >= POOL_BLOCKS) {
        __shared__ float tile[32][33];
        int k  = blockIdx.x - POOL_BLOCKS;   // 0..67
        int x  = tid & 31;
        int y8 = tid >> 5;                   // 0..7

        const float* src; float* dst; int n, tx, ty;
        if (k < 64) { src = Ww; dst = g_WwT; n = D_; tx = k & 7; ty = k >> 3; }
        else        { int q = k - 64; src = Wh; dst = g_WhT; n = T_; tx = q & 1; ty = q >> 1; }

#pragma unroll
        for (int r = 0; r < 4; r++) {
            int row = y8 + r * 8;
            tile[row][x] = src[(ty * 32 + row) * n + tx * 32 + x];
        }
        __syncthreads();
#pragma unroll
        for (int r = 0; r < 4; r++) {
            int row = y8 + r * 8;
            dst[(tx * 32 + row) * n + ty * 32 + x] = tile[x][row];
        }
        return;
    }

    // ---- main pooling path --------------------------------------------------
    int idx = blockIdx.x * 256 + tid;      // over B*T*D/4
    int d4 = idx & (D4_ - 1);
    int t  = (idx >> 6) & (T_ - 1);
    int b  = idx >> 12;
    int lane = tid & 31;
    int wrp  = tid >> 5;

    __shared__ float4 s_col[256];
    __shared__ float  s_warp[8];

    size_t base = (size_t)b * L_ * D4_ + (size_t)t * G_ * D4_ + d4;
    const float4* a4 = reinterpret_cast<const float4*>(aco) + base;
    const float4* v4 = reinterpret_cast<const float4*>(vis) + base;

    float4 sa = make_float4(0.f, 0.f, 0.f, 0.f);
    float4 sv = make_float4(0.f, 0.f, 0.f, 0.f);
#pragma unroll
    for (int g = 0; g < G_; g++) {
        float4 x = ldcs4(a4 + g * D4_);
        float4 y = ldcs4(v4 + g * D4_);
        sa.x += x.x; sa.y += x.y; sa.z += x.z; sa.w += x.w;
        sv.x += y.x; sv.y += y.y; sv.z += y.z; sv.w += y.w;
    }
    const float inv = 1.0f / (float)G_;
    sa.x *= inv; sa.y *= inv; sa.z *= inv; sa.w *= inv;
    sv.x *= inv; sv.y *= inv; sv.z *= inv; sv.w *= inv;

    float4 hw;
    hw.x = 0.5f * (sa.x + sv.x);
    hw.y = 0.5f * (sa.y + sv.y);
    hw.z = 0.5f * (sa.z + sv.z);
    hw.w = 0.5f * (sa.w + sv.w);

    const float cw0 = __ldg(conv_w + 0);
    const float cw1 = __ldg(conv_w + 1);
    const float cb  = __ldg(conv_b + 0);
    const float third = 1.0f / 3.0f;
    float4 c3;
    c3.x = sigmoidf_(fmaf(cw0, sa.x, fmaf(cw1, sv.x, cb))) * third;
    c3.y = sigmoidf_(fmaf(cw0, sa.y, fmaf(cw1, sv.y, cb))) * third;
    c3.z = sigmoidf_(fmaf(cw0, sa.z, fmaf(cw1, sv.z, cb))) * third;
    c3.w = sigmoidf_(fmaf(cw0, sa.w, fmaf(cw1, sv.w, cb))) * third;
    reinterpret_cast<float4*>(g_c3)[idx] = c3;

    float rs = (hw.x + hw.y) + (hw.z + hw.w);
#pragma unroll
    for (int o = 16; o > 0; o >>= 1) rs += __shfl_down_sync(0xffffffffu, rs, o);
    if (lane == 0) s_warp[wrp] = rs;

    s_col[tid] = hw;
    __syncthreads();

    if (tid < 4) {
        g_rowsum[b * T_ + ((blockIdx.x & (PARTS_ - 1)) * 4 + tid)] =
            s_warp[2 * tid] + s_warp[2 * tid + 1];
    }
    if (tid < 64) {
        float4 c0 = s_col[tid];
        float4 c1 = s_col[64 + tid];
        float4 c2 = s_col[128 + tid];
        float4 c3v = s_col[192 + tid];
        float4 cp;
        cp.x = (c0.x + c1.x) + (c2.x + c3v.x);
        cp.y = (c0.y + c1.y) + (c2.y + c3v.y);
        cp.z = (c0.z + c1.z) + (c2.z + c3v.z);
        cp.w = (c0.w + c1.w) + (c2.w + c3v.w);
        reinterpret_cast<float4*>(g_colpart)[blockIdx.x * 64 + tid] = cp;
    }
}

// ---------------------------------------------------------------------------
// Kernel 2: finish means + coalesced matvecs via transposed weights.
// Front-batched bias loads; deep unroll for L2-hit MLP.
// ---------------------------------------------------------------------------
__global__ void __launch_bounds__(256) reduce_kernel(const float* __restrict__ bh,
                                                     const float* __restrict__ bw) {
    int b   = blockIdx.x;
    int tid = threadIdx.x;               // 0..255 (== output index i)

    __shared__ float s_hwm_t[T_];
    __shared__ float s_hwm_d[D_];

    // front-batch the independent loads
    float bw_i = __ldg(bw + tid);
    float bh_i = (tid < T_) ? __ldg(bh + tid) : 0.f;

    if (tid < T_)
        s_hwm_t[tid] = g_rowsum[b * T_ + tid] * (1.0f / (float)D_);

    {
        const float* cp = g_colpart + b * PARTS_ * D_ + tid;
        float cs = 0.f;
#pragma unroll
        for (int p = 0; p < PARTS_; p++) cs += cp[p * D_];
        s_hwm_d[tid] = cs * (1.0f / (float)T_);
    }
    __syncthreads();

    const float third = 1.0f / 3.0f;

    // w3[i] = sigmoid(sum_j hwm_d[j] * WwT[j, i] + bw[i]) / 3
    {
        float acc0 = bw_i, acc1 = 0.f, acc2 = 0.f, acc3 = 0.f;
        const float* wt = g_WwT + tid;
#pragma unroll 16
        for (int j = 0; j < D_; j += 4) {
            acc0 = fmaf(s_hwm_d[j],     __ldg(wt + (j    ) * D_), acc0);
            acc1 = fmaf(s_hwm_d[j + 1], __ldg(wt + (j + 1) * D_), acc1);
            acc2 = fmaf(s_hwm_d[j + 2], __ldg(wt + (j + 2) * D_), acc2);
            acc3 = fmaf(s_hwm_d[j + 3], __ldg(wt + (j + 3) * D_), acc3);
        }
        g_w3[b * D_ + tid] = sigmoidf_((acc0 + acc1) + (acc2 + acc3)) * third;
    }
    // h3[i] = sigmoid(sum_j hwm_t[j] * WhT[j, i] + bh[i]) / 3   (threads 0..63)
    if (tid < T_) {
        float acc0 = bh_i, acc1 = 0.f, acc2 = 0.f, acc3 = 0.f;
        const float* wt = g_WhT + tid;
#pragma unroll 8
        for (int j = 0; j < T_; j += 4) {
            acc0 = fmaf(s_hwm_t[j],     __ldg(wt + (j    ) * T_), acc0);
            acc1 = fmaf(s_hwm_t[j + 1], __ldg(wt + (j + 1) * T_), acc1);
            acc2 = fmaf(s_hwm_t[j + 2], __ldg(wt + (j + 2) * T_), acc2);
            acc3 = fmaf(s_hwm_t[j + 3], __ldg(wt + (j + 3) * T_), acc3);
        }
        g_h3[b * T_ + tid] = sigmoidf_((acc0 + acc1) + (acc2 + acc3)) * third;
    }
}

// ---------------------------------------------------------------------------
// Kernel 3: apply (measured 37.8us, 74.3% DRAM — at mixed R/W ceiling).
// Byte-identical to R12.
// ---------------------------------------------------------------------------
__global__ void __launch_bounds__(256) apply_kernel(const float* __restrict__ aco,
                                                    const float* __restrict__ vis,
                                                    const int* __restrict__ isbag,
                                                    float* __restrict__ out) {
    int base = blockIdx.x * 1024 + threadIdx.x;   // block tile = 1024 float4

    const float4* a4 = reinterpret_cast<const float4*>(aco);
    const float4* v4 = reinterpret_cast<const float4*>(vis);
    const float4* c4 = reinterpret_cast<const float4*>(g_c3);
    const float4* w4 = reinterpret_cast<const float4*>(g_w3);
    float4* o4 = reinterpret_cast<float4*>(out);

    float4 a[4], v[4];
#pragma unroll
    for (int k = 0; k < 4; k++) a[k] = ldcs4(a4 + base + k * 256);
#pragma unroll
    for (int k = 0; k < 4; k++) v[k] = ldcs4(v4 + base + k * 256);

#pragma unroll
    for (int k = 0; k < 4; k++) {
        int idx = base + k * 256;
        int d4 = idx & (D4_ - 1);
        int l  = (idx >> 6) & (L_ - 1);
        int b  = idx >> 15;            // L_*D4_ = 32768 float4 per batch
        int t  = l >> 3;               // t = l / G

        float4 c = __ldg(c4 + ((b * T_ + t) << 6) + d4);
        float4 w = __ldg(w4 + b * D4_ + d4);
        float  h = __ldg(g_h3 + b * T_ + t);
        bool   m = (__ldg(isbag + b * L_ + l) == 1);

        float sx = m ? (h + w.x + c.x) : 1.0f;
        float sy = m ? (h + w.y + c.y) : 1.0f;
        float sz = m ? (h + w.z + c.z) : 1.0f;
        float sw = m ? (h + w.w + c.w) : 1.0f;

        stcs4(o4 + idx,          make_float4(a[k].x * sx, a[k].y * sy, a[k].z * sz, a[k].w * sw));
        stcs4(o4 + idx + NFULL4, make_float4(v[k].x * sx, v[k].y * sy, v[k].z * sz, v[k].w * sw));
    }
}

// ---------------------------------------------------------------------------
extern "C" void kernel_launch(void* const* d_in, const int* in_sizes, int n_in,
                              void* d_out, int out_size) {
    const float* aco    = (const float*)d_in[0];
    const float* vis    = (const float*)d_in[1];
    const int*   isbag  = (const int*)  d_in[2];
    const float* Wh     = (const float*)d_in[3];
    const float* bh     = (const float*)d_in[4];
    const float* Ww     = (const float*)d_in[5];
    const float* bw     = (const float*)d_in[6];
    const float* conv_w = (const float*)d_in[7];
    const float* conv_b = (const float*)d_in[8];
    float* out = (float*)d_out;

    (void)in_sizes; (void)n_in; (void)out_size;

    pool_kernel<<<POOL_BLOCKS + TRANS_BLOCKS, 256>>>(aco, vis, conv_w, conv_b, Wh, Ww);
    reduce_kernel<<<B_, 256>>>(bh, bw);
    apply_kernel<<<NFULL4 / 1024, 256>>>(aco, vis, isbag, out);
}